// round 5
// baseline (speedup 1.0000x reference)
#include <cuda_runtime.h>
#include <cuda_bf16.h>
#include <cstdint>

// Problem constants
#define B_   2
#define S_   2048
#define D_   1024
#define H_   16
#define HD_  64
#define M_   (B_ * S_)   // 4096
#define GN   D_          // 1024
#define GK   D_          // 1024

// ---------------------------------------------------------------------------
// Scratch (no allocations allowed -> __device__ globals)
// ---------------------------------------------------------------------------
__device__ __nv_bfloat16 g_Ahi[M_ * GK];        // hi/lo split of X, later ctx
__device__ __nv_bfloat16 g_Alo[M_ * GK];
__device__ __nv_bfloat16 g_Whi[4][GK * GN];     // weights transposed [N][K]
__device__ __nv_bfloat16 g_Wlo[4][GK * GN];
__device__ __nv_bfloat16 g_Qh[M_ * D_], g_Ql[M_ * D_];   // head layout [bh][s][d]
__device__ __nv_bfloat16 g_Kh[M_ * D_], g_Kl[M_ * D_];
__device__ __nv_bfloat16 g_Vh[M_ * D_], g_Vl[M_ * D_];

// ---------------------------------------------------------------------------
// PTX helpers (sm_80+ features only; tcgen05 is rejected by this harness's
// compute_103 PTX target)
// ---------------------------------------------------------------------------
__device__ __forceinline__ uint32_t smem_u32(const void* p) {
    uint32_t a;
    asm("{ .reg .u64 t; cvta.to.shared.u64 t, %1; cvt.u32.u64 %0, t; }"
        : "=r"(a) : "l"(p));
    return a;
}

#define SW(o) ((o) ^ (((o) >> 3) & 0x70))   // SW128 swizzle

__device__ __forceinline__ void cp16(uint32_t d, const void* g) {
    asm volatile("cp.async.cg.shared.global [%0], [%1], 16;"
                 :: "r"(d), "l"(g) : "memory");
}
#define CP_COMMIT() asm volatile("cp.async.commit_group;" ::: "memory")
#define CP_WAIT1()  asm volatile("cp.async.wait_group 1;" ::: "memory")
#define CP_WAIT2()  asm volatile("cp.async.wait_group 2;" ::: "memory")

__device__ __forceinline__ void ldsm4(uint32_t& r0, uint32_t& r1,
                                      uint32_t& r2, uint32_t& r3, uint32_t a) {
    asm volatile("ldmatrix.sync.aligned.m8n8.x4.shared.b16 {%0,%1,%2,%3}, [%4];"
                 : "=r"(r0), "=r"(r1), "=r"(r2), "=r"(r3) : "r"(a));
}
__device__ __forceinline__ void ldsm4t(uint32_t* r, uint32_t a) {
    asm volatile("ldmatrix.sync.aligned.m8n8.x4.trans.shared.b16 {%0,%1,%2,%3}, [%4];"
                 : "=r"(r[0]), "=r"(r[1]), "=r"(r[2]), "=r"(r[3]) : "r"(a));
}

__device__ __forceinline__ void mma_bf16(float* c, const uint32_t* a,
                                         uint32_t b0, uint32_t b1) {
    asm volatile(
        "mma.sync.aligned.m16n8k16.row.col.f32.bf16.bf16.f32 "
        "{%0,%1,%2,%3}, {%4,%5,%6,%7}, {%8,%9}, {%0,%1,%2,%3};"
        : "+f"(c[0]), "+f"(c[1]), "+f"(c[2]), "+f"(c[3])
        : "r"(a[0]), "r"(a[1]), "r"(a[2]), "r"(a[3]), "r"(b0), "r"(b1));
}

// pack two floats to bf16x2 (a -> low half, b -> high half), round-to-nearest
__device__ __forceinline__ uint32_t pack_bf2(float a, float b) {
    uint32_t d;
    asm("cvt.rn.bf16x2.f32 %0, %1, %2;" : "=r"(d) : "f"(b), "f"(a));
    return d;
}

// truncation split of fp32 v: hi = top 16 bits (bf16), residual returned
__device__ __forceinline__ float trunc_split(float v, uint32_t& hi_bits) {
    hi_bits = __float_as_uint(v) & 0xffff0000u;
    return v - __uint_as_float(hi_bits);
}

// ---------------------------------------------------------------------------
// Conversion kernels
// ---------------------------------------------------------------------------
__global__ __launch_bounds__(256) void split_bf16_kernel(
    const float* __restrict__ in, __nv_bfloat16* __restrict__ hi,
    __nv_bfloat16* __restrict__ lo)
{
    int i = blockIdx.x * 256 + threadIdx.x;
    float4 v = ((const float4*)in)[i];
    uint32_t h0, h1, h2, h3;
    float l0 = trunc_split(v.x, h0);
    float l1 = trunc_split(v.y, h1);
    float l2 = trunc_split(v.z, h2);
    float l3 = trunc_split(v.w, h3);
    uint32_t* H = (uint32_t*)hi;
    uint32_t* L = (uint32_t*)lo;
    H[2 * i]     = __byte_perm(h0, h1, 0x7632);
    H[2 * i + 1] = __byte_perm(h2, h3, 0x7632);
    L[2 * i]     = pack_bf2(l0, l1);
    L[2 * i + 1] = pack_bf2(l2, l3);
}

// W [K][N] f32 -> Whi/Wlo [N][K] bf16 (transpose + split)
__global__ __launch_bounds__(256) void transpose_split_w(
    const float* __restrict__ W, __nv_bfloat16* __restrict__ whi,
    __nv_bfloat16* __restrict__ wlo)
{
    __shared__ float t[32][33];
    const int n0 = blockIdx.x * 32, k0 = blockIdx.y * 32;
    const int tx = threadIdx.x, ty = threadIdx.y;   // (32, 8)
#pragma unroll
    for (int i = 0; i < 32; i += 8)
        t[ty + i][tx] = W[(size_t)(k0 + ty + i) * GN + n0 + tx];
    __syncthreads();
#pragma unroll
    for (int i = 0; i < 32; i += 8) {
        float v = t[tx][ty + i];
        uint32_t hb;
        float l = trunc_split(v, hb);
        size_t off = (size_t)(n0 + ty + i) * GK + k0 + tx;
        whi[off] = __ushort_as_bfloat16((unsigned short)(hb >> 16));
        wlo[off] = __float2bfloat16(l);
    }
}

// ---------------------------------------------------------------------------
// bf16 mma.sync GEMM, 3-pass hi/lo split, 128x128 tile, 8 warps, 3-stage async
// mode 0: fp32 row-major C[M,N]
// mode 1: bf16 hi/lo split outputs scattered to head layout [B,H,S,hd]
// ---------------------------------------------------------------------------
#define LOAD_CHUNK(c) do {                                                   \
    int ph_ = (c) >> 4, kc_ = ((c) & 15) * 64;                               \
    const __nv_bfloat16* As_ = (ph_ == 2) ? Alo : Ahi;                       \
    const __nv_bfloat16* Bs_ = (ph_ == 1) ? Blo : Bhi;                       \
    uint32_t st_ = sb + ((c) % 3) * 32768;                                   \
    const __nv_bfloat16* ga_ = As_ + (size_t)(m0 + lrow) * GK + kc_ + lhalf * 32; \
    const __nv_bfloat16* gb_ = Bs_ + (size_t)(n0 + lrow) * GK + kc_ + lhalf * 32; \
    uint32_t ob_ = lrow * 128 + lhalf * 64;                                  \
    _Pragma("unroll")                                                        \
    for (int q_ = 0; q_ < 4; q_++) {                                         \
        cp16(st_ + SW(ob_ + q_ * 16), ga_ + q_ * 8);                         \
        cp16(st_ + 16384 + SW(ob_ + q_ * 16), gb_ + q_ * 8);                 \
    }                                                                        \
} while (0)

__global__ __launch_bounds__(256) void gemm_tc(
    const __nv_bfloat16* __restrict__ Ahi, const __nv_bfloat16* __restrict__ Alo,
    const __nv_bfloat16* __restrict__ Bhi, const __nv_bfloat16* __restrict__ Blo,
    const float* __restrict__ bias, float* __restrict__ C,
    __nv_bfloat16* __restrict__ Chi, __nv_bfloat16* __restrict__ Clo, int mode)
{
    extern __shared__ char smc[];
    const uint32_t sb = smem_u32(smc);
    const int tid = threadIdx.x, lane = tid & 31, wid = tid >> 5;
    const int m0 = blockIdx.y * 128, n0 = blockIdx.x * 128;
    const int wm = (wid & 3) * 32, wn = (wid >> 2) * 64;
    const int lrow = tid >> 1, lhalf = tid & 1;

    float acc[2][8][4];
#pragma unroll
    for (int mi = 0; mi < 2; mi++)
#pragma unroll
        for (int ni = 0; ni < 8; ni++)
#pragma unroll
            for (int r = 0; r < 4; r++) acc[mi][ni][r] = 0.0f;

    uint32_t aoff[2], boff[4];
#pragma unroll
    for (int mi = 0; mi < 2; mi++) {
        int r = wm + mi * 16 + (lane & 15);
        aoff[mi] = r * 128 + ((lane >> 4) << 4);
    }
#pragma unroll
    for (int nt = 0; nt < 4; nt++) {
        int n = wn + nt * 16 + (lane & 7) + ((lane >> 4) << 3);
        boff[nt] = n * 128 + (((lane >> 3) & 1) << 4);
    }

    LOAD_CHUNK(0); CP_COMMIT();
    LOAD_CHUNK(1); CP_COMMIT();

    for (int c = 0; c < 48; c++) {
        if (c + 2 < 48) LOAD_CHUNK(c + 2);
        CP_COMMIT();
        CP_WAIT2();
        __syncthreads();

        const uint32_t sa = sb + (c % 3) * 32768;
        const uint32_t sB = sa + 16384;
#pragma unroll
        for (int k16 = 0; k16 < 4; k16++) {
            const uint32_t kb = k16 * 32;
            uint32_t a[2][4];
            ldsm4(a[0][0], a[0][1], a[0][2], a[0][3], sa + SW(aoff[0] + kb));
            ldsm4(a[1][0], a[1][1], a[1][2], a[1][3], sa + SW(aoff[1] + kb));
            uint32_t bf[4][4];
#pragma unroll
            for (int nt = 0; nt < 4; nt++)
                ldsm4(bf[nt][0], bf[nt][1], bf[nt][2], bf[nt][3],
                      sB + SW(boff[nt] + kb));
#pragma unroll
            for (int mi = 0; mi < 2; mi++)
#pragma unroll
                for (int ni = 0; ni < 8; ni++)
                    mma_bf16(acc[mi][ni], a[mi],
                             bf[ni >> 1][(ni & 1) * 2],
                             bf[ni >> 1][(ni & 1) * 2 + 1]);
        }
        __syncthreads();
    }

    // Epilogue
    const int r0 = lane >> 2, cq = (lane & 3) * 2;
#pragma unroll
    for (int mi = 0; mi < 2; mi++) {
#pragma unroll
        for (int ni = 0; ni < 8; ni++) {
            const int rr = m0 + wm + mi * 16 + r0;
            const int cc = n0 + wn + ni * 8 + cq;
            const float2 bv = *(const float2*)&bias[cc];
            float v0 = acc[mi][ni][0] + bv.x, v1 = acc[mi][ni][1] + bv.y;
            float v2 = acc[mi][ni][2] + bv.x, v3 = acc[mi][ni][3] + bv.y;
            if (mode == 0) {
                *(float2*)&C[(size_t)rr * GN + cc] = make_float2(v0, v1);
                *(float2*)&C[(size_t)(rr + 8) * GN + cc] = make_float2(v2, v3);
            } else {
                const int h = cc >> 6, d = cc & 63;
                const int bb = rr >> 11;
                const int s0 = rr & 2047, s1 = (rr + 8) & 2047;
                const size_t o0 = ((((size_t)bb * H_ + h) * S_ + s0) << 6) + d;
                const size_t o1 = ((((size_t)bb * H_ + h) * S_ + s1) << 6) + d;
                uint32_t h0, h1, h2, h3;
                float l0 = trunc_split(v0, h0), l1 = trunc_split(v1, h1);
                float l2 = trunc_split(v2, h2), l3 = trunc_split(v3, h3);
                *(uint32_t*)(Chi + o0) = __byte_perm(h0, h1, 0x7632);
                *(uint32_t*)(Chi + o1) = __byte_perm(h2, h3, 0x7632);
                *(uint32_t*)(Clo + o0) = pack_bf2(l0, l1);
                *(uint32_t*)(Clo + o1) = pack_bf2(l2, l3);
            }
        }
    }
}

// ---------------------------------------------------------------------------
// Tensor-core flash attention.
// CTA: 128 q-rows x one (b,h). 8 warps, each 16 q-rows.
// k-tiles of 64, double-buffered (Khi|Klo|Vhi|Vlo = 32KB/stage).
// S = QhiKhi + QhiKlo + QloKhi;  O += PhiVhi + PhiVlo + PloVhi.
// Register-resident online softmax on mma accumulator layout.
// Writes ctx as bf16 hi/lo in [B,S,D] layout (input of Wo gemm).
// ---------------------------------------------------------------------------
#define ATT_STAGE(kt) do {                                                   \
    int s_ = (kt) & 1; int k0_ = (kt) * 64;                                  \
    uint32_t st_ = SST + s_ * 32768;                                         \
    const size_t roff_ = base + (size_t)k0_ * HD_;                           \
    _Pragma("unroll")                                                        \
    for (int i_ = 0; i_ < 2; i_++) {                                         \
        int idx_ = tid + i_ * 256;                                           \
        int r_ = idx_ >> 3, u_ = idx_ & 7;                                   \
        uint32_t so_ = SW((uint32_t)(r_ * 128 + u_ * 16));                   \
        size_t go_ = roff_ + (size_t)r_ * HD_ + u_ * 8;                      \
        cp16(st_ + so_,          Kh_ + go_);                                 \
        cp16(st_ + 8192 + so_,   Kl_ + go_);                                 \
        cp16(st_ + 16384 + so_,  Vh_ + go_);                                 \
        cp16(st_ + 24576 + so_,  Vl_ + go_);                                 \
    }                                                                        \
    if (tid < 64)                                                            \
        smaskf[s_ * 64 + tid] = (1.0f - mask[b * S_ + k0_ + tid]) * -10000.0f; \
} while (0)

__global__ __launch_bounds__(256) void attn_tc(
    const __nv_bfloat16* __restrict__ Qh_, const __nv_bfloat16* __restrict__ Ql_,
    const __nv_bfloat16* __restrict__ Kh_, const __nv_bfloat16* __restrict__ Kl_,
    const __nv_bfloat16* __restrict__ Vh_, const __nv_bfloat16* __restrict__ Vl_,
    const float* __restrict__ mask,
    __nv_bfloat16* __restrict__ ctxh, __nv_bfloat16* __restrict__ ctxl)
{
    extern __shared__ char smraw[];
    const uint32_t sb = smem_u32(smraw);
    const uint32_t SQH = sb, SQL = sb + 16384;
    const uint32_t SST = sb + 32768;                    // 2 stages x 32KB
    float* smaskf = (float*)(smraw + 98304);            // 2 x 64 floats

    const int tid = threadIdx.x, lane = tid & 31, wid = tid >> 5;
    const int qt = gridDim.x - 1 - blockIdx.x;          // heavy tiles first
    const int q0 = qt * 128;
    const int bh = blockIdx.y;
    const int b = bh >> 4, hh = bh & 15;
    const size_t base = (size_t)bh * (S_ * HD_);
    const int wq = wid * 16;

    // Q tile (hi+lo), 128 x 64 bf16, SW128 rows
    {
        const size_t qoff = base + (size_t)q0 * HD_;
#pragma unroll
        for (int i = 0; i < 4; i++) {
            int idx = tid + i * 256;
            int r = idx >> 3, u = idx & 7;
            uint32_t so = SW((uint32_t)(r * 128 + u * 16));
            cp16(SQH + so, Qh_ + qoff + (size_t)r * HD_ + u * 8);
            cp16(SQL + so, Ql_ + qoff + (size_t)r * HD_ + u * 8);
        }
    }
    ATT_STAGE(0);
    CP_COMMIT();           // group 0 = Q + stage 0

    // per-lane fragment addressing
    const uint32_t arow = (wq + (lane & 15)) * 128 + ((lane >> 4) << 4);
    const uint32_t bno  = ((lane & 7) + ((lane >> 4) << 3)) * 128
                        + (((lane >> 3) & 1) << 4);
    const uint32_t vro  = (((lane >> 3) & 1) * 8 + (lane & 7)) * 128
                        + ((lane >> 4) << 4);
    const int c0  = (lane & 3) * 2;
    const int rg0 = q0 + wq + (lane >> 2);
    const int rg1 = rg0 + 8;

    float o[8][4];
#pragma unroll
    for (int ni = 0; ni < 8; ni++)
#pragma unroll
        for (int r = 0; r < 4; r++) o[ni][r] = 0.0f;
    float m0r = -1e30f, m1r = -1e30f, l0r = 0.0f, l1r = 0.0f;

    const int ntile = 2 * qt + 2;
    for (int kt = 0; kt < ntile; kt++) {
        if (kt + 1 < ntile) ATT_STAGE(kt + 1);
        CP_COMMIT();
        CP_WAIT1();
        __syncthreads();

        const int k0 = kt * 64;
        if (k0 <= q0 + wq + 15) {       // skip tiles fully above the diagonal
            const uint32_t sKh = SST + (kt & 1) * 32768;
            const uint32_t sKl = sKh + 8192;
            const uint32_t sVh = sKh + 16384;
            const uint32_t sVl = sKh + 24576;

            float s[8][4];
#pragma unroll
            for (int ni = 0; ni < 8; ni++)
#pragma unroll
                for (int r = 0; r < 4; r++) s[ni][r] = 0.0f;

            // ---- S = Q.K^T (3 split passes) ----
#pragma unroll
            for (int k16 = 0; k16 < 4; k16++) {
                const uint32_t kb = k16 * 32;
                uint32_t aH[4], aL[4], kf[4][4];
                ldsm4(aH[0], aH[1], aH[2], aH[3], SQH + SW(arow + kb));
                ldsm4(aL[0], aL[1], aL[2], aL[3], SQL + SW(arow + kb));
#pragma unroll
                for (int nt = 0; nt < 4; nt++)
                    ldsm4(kf[nt][0], kf[nt][1], kf[nt][2], kf[nt][3],
                          sKh + SW(bno + nt * 2048 + kb));
#pragma unroll
                for (int ni = 0; ni < 8; ni++)
                    mma_bf16(s[ni], aH, kf[ni >> 1][(ni & 1) * 2],
                             kf[ni >> 1][(ni & 1) * 2 + 1]);
#pragma unroll
                for (int ni = 0; ni < 8; ni++)
                    mma_bf16(s[ni], aL, kf[ni >> 1][(ni & 1) * 2],
                             kf[ni >> 1][(ni & 1) * 2 + 1]);
#pragma unroll
                for (int nt = 0; nt < 4; nt++)
                    ldsm4(kf[nt][0], kf[nt][1], kf[nt][2], kf[nt][3],
                          sKl + SW(bno + nt * 2048 + kb));
#pragma unroll
                for (int ni = 0; ni < 8; ni++)
                    mma_bf16(s[ni], aH, kf[ni >> 1][(ni & 1) * 2],
                             kf[ni >> 1][(ni & 1) * 2 + 1]);
            }

            // ---- scale + pad + causal ----
            const float* mrow = smaskf + (kt & 1) * 64;
            const bool needc = (k0 + 63 > q0 + wq);
#pragma unroll
            for (int ni = 0; ni < 8; ni++) {
                const int kg = k0 + ni * 8 + c0;
                const float ma = mrow[ni * 8 + c0];
                const float mb = mrow[ni * 8 + c0 + 1];
                s[ni][0] = s[ni][0] * 0.125f + ma;
                s[ni][1] = s[ni][1] * 0.125f + mb;
                s[ni][2] = s[ni][2] * 0.125f + ma;
                s[ni][3] = s[ni][3] * 0.125f + mb;
                if (needc) {
                    if (kg > rg0)     s[ni][0] -= 1e10f;
                    if (kg + 1 > rg0) s[ni][1] -= 1e10f;
                    if (kg > rg1)     s[ni][2] -= 1e10f;
                    if (kg + 1 > rg1) s[ni][3] -= 1e10f;
                }
            }

            // ---- register online softmax (rows rg0, rg1 per lane) ----
            float mx0 = -1e30f, mx1 = -1e30f;
#pragma unroll
            for (int ni = 0; ni < 8; ni++) {
                mx0 = fmaxf(mx0, fmaxf(s[ni][0], s[ni][1]));
                mx1 = fmaxf(mx1, fmaxf(s[ni][2], s[ni][3]));
            }
            mx0 = fmaxf(mx0, __shfl_xor_sync(0xffffffffu, mx0, 1));
            mx0 = fmaxf(mx0, __shfl_xor_sync(0xffffffffu, mx0, 2));
            mx1 = fmaxf(mx1, __shfl_xor_sync(0xffffffffu, mx1, 1));
            mx1 = fmaxf(mx1, __shfl_xor_sync(0xffffffffu, mx1, 2));
            const float nm0 = fmaxf(m0r, mx0), nm1 = fmaxf(m1r, mx1);
            const float al0 = __expf(m0r - nm0), al1 = __expf(m1r - nm1);
            float ps0 = 0.0f, ps1 = 0.0f;
#pragma unroll
            for (int ni = 0; ni < 8; ni++) {
                s[ni][0] = __expf(s[ni][0] - nm0); ps0 += s[ni][0];
                s[ni][1] = __expf(s[ni][1] - nm0); ps0 += s[ni][1];
                s[ni][2] = __expf(s[ni][2] - nm1); ps1 += s[ni][2];
                s[ni][3] = __expf(s[ni][3] - nm1); ps1 += s[ni][3];
            }
            ps0 += __shfl_xor_sync(0xffffffffu, ps0, 1);
            ps0 += __shfl_xor_sync(0xffffffffu, ps0, 2);
            ps1 += __shfl_xor_sync(0xffffffffu, ps1, 1);
            ps1 += __shfl_xor_sync(0xffffffffu, ps1, 2);
            l0r = l0r * al0 + ps0;  m0r = nm0;
            l1r = l1r * al1 + ps1;  m1r = nm1;
#pragma unroll
            for (int ni = 0; ni < 8; ni++) {
                o[ni][0] *= al0; o[ni][1] *= al0;
                o[ni][2] *= al1; o[ni][3] *= al1;
            }

            // ---- O += P.V (3 split passes) ----
#pragma unroll
            for (int jb = 0; jb < 4; jb++) {
                uint32_t aPh[4], aPl[4];
#pragma unroll
                for (int t = 0; t < 2; t++) {
                    const int ti = jb * 2 + t;
                    uint32_t u0, u1, u2, u3;
                    float l0 = trunc_split(s[ti][0], u0);
                    float l1 = trunc_split(s[ti][1], u1);
                    float l2 = trunc_split(s[ti][2], u2);
                    float l3 = trunc_split(s[ti][3], u3);
                    aPh[t * 2 + 0] = __byte_perm(u0, u1, 0x7632);
                    aPh[t * 2 + 1] = __byte_perm(u2, u3, 0x7632);
                    aPl[t * 2 + 0] = pack_bf2(l0, l1);
                    aPl[t * 2 + 1] = pack_bf2(l2, l3);
                }
                uint32_t vf[4][4];
                const uint32_t vbase = vro + jb * 2048;
#pragma unroll
                for (int nt = 0; nt < 4; nt++)
                    ldsm4t(vf[nt], sVh + SW(vbase + nt * 32));
#pragma unroll
                for (int ni = 0; ni < 8; ni++)
                    mma_bf16(o[ni], aPh, vf[ni >> 1][(ni & 1) * 2],
                             vf[ni >> 1][(ni & 1) * 2 + 1]);
#pragma unroll
                for (int ni = 0; ni < 8; ni++)
                    mma_bf16(o[ni], aPl, vf[ni >> 1][(ni & 1) * 2],
                             vf[ni >> 1][(ni & 1) * 2 + 1]);
#pragma unroll
                for (int nt = 0; nt < 4; nt++)
                    ldsm4t(vf[nt], sVl + SW(vbase + nt * 32));
#pragma unroll
                for (int ni = 0; ni < 8; ni++)
                    mma_bf16(o[ni], aPh, vf[ni >> 1][(ni & 1) * 2],
                             vf[ni >> 1][(ni & 1) * 2 + 1]);
            }
        }
        __syncthreads();
    }

    // ---- normalize + write ctx hi/lo in [B,S,D] layout ----
    const float i0 = 1.0f / l0r, i1 = 1.0f / l1r;
    const size_t row0 = ((size_t)b * S_ + rg0) * D_ + hh * HD_;
    const size_t row1 = ((size_t)b * S_ + rg1) * D_ + hh * HD_;
#pragma unroll
    for (int ni = 0; ni < 8; ni++) {
        const int d = ni * 8 + c0;
        float v0 = o[ni][0] * i0, v1 = o[ni][1] * i0;
        float v2 = o[ni][2] * i1, v3 = o[ni][3] * i1;
        uint32_t u0, u1, u2, u3;
        float l0 = trunc_split(v0, u0), l1 = trunc_split(v1, u1);
        float l2 = trunc_split(v2, u2), l3 = trunc_split(v3, u3);
        *(uint32_t*)(ctxh + row0 + d) = __byte_perm(u0, u1, 0x7632);
        *(uint32_t*)(ctxh + row1 + d) = __byte_perm(u2, u3, 0x7632);
        *(uint32_t*)(ctxl + row0 + d) = pack_bf2(l0, l1);
        *(uint32_t*)(ctxl + row1 + d) = pack_bf2(l2, l3);
    }
}

// ---------------------------------------------------------------------------
extern "C" void kernel_launch(void* const* d_in, const int* in_sizes, int n_in,
                              void* d_out, int out_size)
{
    const float* X    = (const float*)d_in[0];
    const float* mask = (const float*)d_in[1];
    const float* Wq   = (const float*)d_in[2];
    const float* bq   = (const float*)d_in[3];
    const float* Wk   = (const float*)d_in[4];
    const float* bk   = (const float*)d_in[5];
    const float* Wv   = (const float*)d_in[6];
    const float* bv   = (const float*)d_in[7];
    const float* Wo   = (const float*)d_in[8];
    const float* bo   = (const float*)d_in[9];
    float* out = (float*)d_out;

    __nv_bfloat16 *pAh, *pAl, *pWh, *pWl, *pQh, *pQl, *pKh, *pKl, *pVh, *pVl;
    cudaGetSymbolAddress((void**)&pAh, g_Ahi);
    cudaGetSymbolAddress((void**)&pAl, g_Alo);
    cudaGetSymbolAddress((void**)&pWh, g_Whi);
    cudaGetSymbolAddress((void**)&pWl, g_Wlo);
    cudaGetSymbolAddress((void**)&pQh, g_Qh);
    cudaGetSymbolAddress((void**)&pQl, g_Ql);
    cudaGetSymbolAddress((void**)&pKh, g_Kh);
    cudaGetSymbolAddress((void**)&pKl, g_Kl);
    cudaGetSymbolAddress((void**)&pVh, g_Vh);
    cudaGetSymbolAddress((void**)&pVl, g_Vl);

    const int GEMM_SMEM = 3 * 32768;                    // 96 KB
    cudaFuncSetAttribute(gemm_tc,
                         cudaFuncAttributeMaxDynamicSharedMemorySize, GEMM_SMEM);
    const int ATTN_SMEM = 98304 + 512;                  // Q 32K + 2x32K + mask
    cudaFuncSetAttribute(attn_tc,
                         cudaFuncAttributeMaxDynamicSharedMemorySize, ATTN_SMEM);

    const size_t WSZ = (size_t)GK * GN;
    const float* Ws[4] = {Wq, Wk, Wv, Wo};

    split_bf16_kernel<<<M_ * GK / 1024, 256>>>(X, pAh, pAl);
    dim3 tb(32, 8), tg(GN / 32, GK / 32);
    for (int i = 0; i < 4; i++)
        transpose_split_w<<<tg, tb>>>(Ws[i], pWh + i * WSZ, pWl + i * WSZ);

    dim3 gg(GN / 128, M_ / 128);   // (8, 32)
    gemm_tc<<<gg, 256, GEMM_SMEM>>>(pAh, pAl, pWh + 0 * WSZ, pWl + 0 * WSZ,
                                    bq, nullptr, pQh, pQl, 1);
    gemm_tc<<<gg, 256, GEMM_SMEM>>>(pAh, pAl, pWh + 1 * WSZ, pWl + 1 * WSZ,
                                    bk, nullptr, pKh, pKl, 1);
    gemm_tc<<<gg, 256, GEMM_SMEM>>>(pAh, pAl, pWh + 2 * WSZ, pWl + 2 * WSZ,
                                    bv, nullptr, pVh, pVl, 1);

    dim3 ga(S_ / 128, B_ * H_);    // (16, 32)
    attn_tc<<<ga, 256, ATTN_SMEM>>>(pQh, pQl, pKh, pKl, pVh, pVl, mask,
                                    pAh, pAl);   // ctx overwrites X split

    gemm_tc<<<gg, 256, GEMM_SMEM>>>(pAh, pAl, pWh + 3 * WSZ, pWl + 3 * WSZ,
                                    bo, out, nullptr, nullptr, 0);
}